// round 6
// baseline (speedup 1.0000x reference)
#include <cuda_runtime.h>
#include <cuda_bf16.h>
#include <math.h>
#include <stdint.h>

#define BATCH   2
#define LSEQ    2048
#define DM      1024
#define DI      2048
#define DSTATE  64
#define HD      64
#define NH      32
#define CONVDIM 2176
#define DINPROJ 4256
#define ROWS    (BATCH*LSEQ)
#define EPSF    1e-5f

// ---------------- fp32 scratch ----------------
__device__ float g_zx [(size_t)ROWS*DINPROJ];
__device__ float g_xbc[(size_t)ROWS*CONVDIM];
__device__ float g_dt [(size_t)ROWS*NH];
__device__ float g_y  [(size_t)ROWS*DI];
__device__ float g_x1 [(size_t)ROWS*DM];

// ---------------- bf16 split scratch (hi/lo) ----------------
__device__ __nv_bfloat16 w_ip_hi[(size_t)DINPROJ*DM],  w_ip_lo[(size_t)DINPROJ*DM];
__device__ __nv_bfloat16 w_op_hi[(size_t)DM*DI],       w_op_lo[(size_t)DM*DI];
__device__ __nv_bfloat16 w_m1_hi[(size_t)4*DM*DM],     w_m1_lo[(size_t)4*DM*DM];
__device__ __nv_bfloat16 w_m2_hi[(size_t)DM*4*DM],     w_m2_lo[(size_t)DM*4*DM];
__device__ __nv_bfloat16 a_ln1_hi[(size_t)ROWS*DM],    a_ln1_lo[(size_t)ROWS*DM];
__device__ __nv_bfloat16 a_y_hi [(size_t)ROWS*DI],     a_y_lo [(size_t)ROWS*DI];
__device__ __nv_bfloat16 a_ln2_hi[(size_t)ROWS*DM],    a_ln2_lo[(size_t)ROWS*DM];
__device__ __nv_bfloat16 a_mlp_hi[(size_t)ROWS*4*DM],  a_mlp_lo[(size_t)ROWS*4*DM];

// ---------------- helpers ----------------
__device__ __forceinline__ uint32_t smem_u32(const void* p) {
    uint32_t a;
    asm("{ .reg .u64 t; cvta.to.shared.u64 t, %1; cvt.u32.u64 %0, t; }" : "=r"(a) : "l"(p));
    return a;
}
__device__ __forceinline__ void cp_async16(uint32_t saddr, const void* gaddr, uint32_t sz) {
    asm volatile("cp.async.cg.shared.global [%0], [%1], 16, %2;"
                 :: "r"(saddr), "l"(gaddr), "r"(sz));
}
__device__ __forceinline__ void cp_commit() { asm volatile("cp.async.commit_group;"); }
template<int N> __device__ __forceinline__ void cp_wait() {
    asm volatile("cp.async.wait_group %0;" :: "n"(N));
}
__device__ __forceinline__ void ldm_x4(uint32_t addr, uint32_t& r0, uint32_t& r1,
                                       uint32_t& r2, uint32_t& r3) {
    asm volatile("ldmatrix.sync.aligned.m8n8.x4.shared.b16 {%0,%1,%2,%3}, [%4];"
                 : "=r"(r0), "=r"(r1), "=r"(r2), "=r"(r3) : "r"(addr));
}
__device__ __forceinline__ void mma_bf16(float* c, const uint32_t* a, const uint32_t* b) {
    asm volatile(
        "mma.sync.aligned.m16n8k16.row.col.f32.bf16.bf16.f32 "
        "{%0,%1,%2,%3}, {%4,%5,%6,%7}, {%8,%9}, {%0,%1,%2,%3};"
        : "+f"(c[0]), "+f"(c[1]), "+f"(c[2]), "+f"(c[3])
        : "r"(a[0]), "r"(a[1]), "r"(a[2]), "r"(a[3]), "r"(b[0]), "r"(b[1]));
}
__device__ __forceinline__ void split1(float v, __nv_bfloat16& h, __nv_bfloat16& l) {
    h = __float2bfloat16(v);
    l = __float2bfloat16(v - __bfloat162float(h));
}

// ---------------- vectorized weight split ----------------
__global__ void cvt_kernel(const float4* __restrict__ in, uint2* __restrict__ hi,
                           uint2* __restrict__ lo, size_t n4)
{
    size_t i = (size_t)blockIdx.x * blockDim.x + threadIdx.x;
    size_t stride = (size_t)gridDim.x * blockDim.x;
    for (; i < n4; i += stride) {
        float4 v = in[i];
        __nv_bfloat16 h0,h1,h2,h3,l0,l1,l2,l3;
        split1(v.x,h0,l0); split1(v.y,h1,l1); split1(v.z,h2,l2); split1(v.w,h3,l3);
        __nv_bfloat162 hA = __halves2bfloat162(h0,h1), hB = __halves2bfloat162(h2,h3);
        __nv_bfloat162 lA = __halves2bfloat162(l0,l1), lB = __halves2bfloat162(l2,l3);
        hi[i] = make_uint2(*(uint32_t*)&hA, *(uint32_t*)&hB);
        lo[i] = make_uint2(*(uint32_t*)&lA, *(uint32_t*)&lB);
    }
}

// ---------------- layernorm + split (bf16 hi/lo out) ----------------
__global__ void ln_split_kernel(const float* __restrict__ in, const float* __restrict__ w,
                                const float* __restrict__ b,
                                __nv_bfloat16* __restrict__ hi, __nv_bfloat16* __restrict__ lo)
{
    int row = blockIdx.x;
    const float* x = in + (size_t)row*DM;
    int c0 = threadIdx.x * 4;
    float4 v = *(const float4*)(x + c0);
    float s  = v.x + v.y + v.z + v.w;
    float ss = v.x*v.x + v.y*v.y + v.z*v.z + v.w*v.w;
    __shared__ float red0[8], red1[8];
    #pragma unroll
    for (int o = 16; o; o >>= 1) {
        s  += __shfl_xor_sync(0xffffffffu, s, o);
        ss += __shfl_xor_sync(0xffffffffu, ss, o);
    }
    int warp = threadIdx.x >> 5, lane = threadIdx.x & 31;
    if (lane == 0) { red0[warp] = s; red1[warp] = ss; }
    __syncthreads();
    s = 0.f; ss = 0.f;
    #pragma unroll
    for (int i = 0; i < 8; i++) { s += red0[i]; ss += red1[i]; }
    float mu  = s * (1.f/DM);
    float var = ss * (1.f/DM) - mu*mu;
    float sc  = rsqrtf(var + EPSF);
    float4 wv = *(const float4*)(w + c0);
    float4 bv = *(const float4*)(b + c0);
    float o0 = (v.x-mu)*sc*wv.x + bv.x;
    float o1 = (v.y-mu)*sc*wv.y + bv.y;
    float o2 = (v.z-mu)*sc*wv.z + bv.z;
    float o3 = (v.w-mu)*sc*wv.w + bv.w;
    __nv_bfloat16 h0,h1,h2,h3,l0,l1,l2,l3;
    split1(o0,h0,l0); split1(o1,h1,l1); split1(o2,h2,l2); split1(o3,h3,l3);
    __nv_bfloat162 hA = __halves2bfloat162(h0,h1), hB = __halves2bfloat162(h2,h3);
    __nv_bfloat162 lA = __halves2bfloat162(l0,l1), lB = __halves2bfloat162(l2,l3);
    size_t ob = (size_t)row*DM + c0;
    *(uint2*)(hi + ob) = make_uint2(*(uint32_t*)&hA, *(uint32_t*)&hB);
    *(uint2*)(lo + ob) = make_uint2(*(uint32_t*)&lA, *(uint32_t*)&lB);
}

// ---------------- HMMA split-bf16 GEMM: C[M,N] = A[M,K] @ B[N,K]^T ----------------
// 128x128 tile, BK=32, 4-stage cp.async pipeline, one barrier per k-chunk.
// Term-major MMA ordering: 16 independent accumulators between dependent MMAs.
// EPI: 0=plain fp32, 1=fp32+add, 2=bias+gelu -> bf16 hi/lo split out, 3=fp32+bias+add
#define PITCHB   80
#define MATB     (128*PITCHB)
#define STAGEB   (4*MATB)        // 40960
#define NSTAGE   4
#define GSMEM_BYTES (NSTAGE*STAGEB)  // 163840

template<int EPI>
__global__ void __launch_bounds__(256, 1)
gemm_tc(const __nv_bfloat16* __restrict__ Ahi, const __nv_bfloat16* __restrict__ Alo,
        const __nv_bfloat16* __restrict__ Bhi, const __nv_bfloat16* __restrict__ Blo,
        float* __restrict__ C, int M, int N, int K,
        const float* __restrict__ add, const float* __restrict__ bias,
        __nv_bfloat16* __restrict__ Ohi, __nv_bfloat16* __restrict__ Olo)
{
    extern __shared__ __align__(128) char smem[];
    uint32_t sb = smem_u32(smem);
    int tid = threadIdx.x, wid = tid >> 5, lane = tid & 31;
    int bm = blockIdx.y * 128, bn = blockIdx.x * 128;
    int warp_m = wid >> 2, warp_n = wid & 3;
    int nrow_b = N - bn;

    int lr0 = tid >> 2, lc0 = (tid & 3);
    int lr1 = (tid + 256) >> 2, lc1 = (tid & 3);

    const int NK = K >> 5;

    auto issue_load = [&](int kc) {
        uint32_t s0 = sb + (kc % NSTAGE) * STAGEB;
        int k0 = kc << 5;
        {
            size_t ga0 = (size_t)(bm + lr0) * K + k0 + lc0 * 8;
            size_t ga1 = (size_t)(bm + lr1) * K + k0 + lc1 * 8;
            cp_async16(s0 + 0*MATB + lr0*PITCHB + lc0*16, Ahi + ga0, 16);
            cp_async16(s0 + 0*MATB + lr1*PITCHB + lc1*16, Ahi + ga1, 16);
            cp_async16(s0 + 1*MATB + lr0*PITCHB + lc0*16, Alo + ga0, 16);
            cp_async16(s0 + 1*MATB + lr1*PITCHB + lc1*16, Alo + ga1, 16);
        }
        {
            int r0 = lr0 < nrow_b ? lr0 : 0;  uint32_t z0 = lr0 < nrow_b ? 16u : 0u;
            int r1 = lr1 < nrow_b ? lr1 : 0;  uint32_t z1 = lr1 < nrow_b ? 16u : 0u;
            size_t gb0 = (size_t)(bn + r0) * K + k0 + lc0 * 8;
            size_t gb1 = (size_t)(bn + r1) * K + k0 + lc1 * 8;
            cp_async16(s0 + 2*MATB + lr0*PITCHB + lc0*16, Bhi + gb0, z0);
            cp_async16(s0 + 2*MATB + lr1*PITCHB + lc1*16, Bhi + gb1, z1);
            cp_async16(s0 + 3*MATB + lr0*PITCHB + lc0*16, Blo + gb0, z0);
            cp_async16(s0 + 3*MATB + lr1*PITCHB + lc1*16, Blo + gb1, z1);
        }
        cp_commit();
    };

    float acc[4][4][4];
    #pragma unroll
    for (int i = 0; i < 4; i++)
        #pragma unroll
        for (int j = 0; j < 4; j++)
            #pragma unroll
            for (int q = 0; q < 4; q++) acc[i][j][q] = 0.f;

    issue_load(0);
    if (NK > 1) issue_load(1);
    if (NK > 2) issue_load(2);

    int a_row = warp_m * 64 + (lane & 15);
    int a_colb = ((lane >> 4) << 3) * 2;
    int b_row = warp_n * 32 + ((lane >> 4) << 3) + (lane & 7);
    int b_colb = (((lane >> 3) & 1) << 3) * 2;

    for (int kc = 0; kc < NK; kc++) {
        uint32_t s0 = sb + (kc % NSTAGE) * STAGEB;
        if (kc + 2 < NK) cp_wait<2>();
        else if (kc + 1 < NK) cp_wait<1>();
        else cp_wait<0>();
        __syncthreads();
        if (kc + 3 < NK) issue_load(kc + 3);

        #pragma unroll
        for (int ks = 0; ks < 2; ks++) {
            uint32_t ah[4][4], al[4][4], bh[4][2], bl[4][2];
            #pragma unroll
            for (int mt = 0; mt < 4; mt++) {
                uint32_t ad = s0 + 0*MATB + (a_row + mt*16)*PITCHB + a_colb + ks*32;
                ldm_x4(ad, ah[mt][0], ah[mt][1], ah[mt][2], ah[mt][3]);
                ldm_x4(ad + MATB, al[mt][0], al[mt][1], al[mt][2], al[mt][3]);
            }
            #pragma unroll
            for (int nh = 0; nh < 2; nh++) {
                uint32_t bd = s0 + 2*MATB + (b_row + nh*16)*PITCHB + b_colb + ks*32;
                ldm_x4(bd, bh[nh*2][0], bh[nh*2][1], bh[nh*2+1][0], bh[nh*2+1][1]);
                ldm_x4(bd + MATB, bl[nh*2][0], bl[nh*2][1], bl[nh*2+1][0], bl[nh*2+1][1]);
            }
            // term-major: all hi*hi, then all hi*lo, then all lo*hi
            #pragma unroll
            for (int mt = 0; mt < 4; mt++)
                #pragma unroll
                for (int nt = 0; nt < 4; nt++)
                    mma_bf16(acc[mt][nt], ah[mt], bh[nt]);
            #pragma unroll
            for (int mt = 0; mt < 4; mt++)
                #pragma unroll
                for (int nt = 0; nt < 4; nt++)
                    mma_bf16(acc[mt][nt], ah[mt], bl[nt]);
            #pragma unroll
            for (int mt = 0; mt < 4; mt++)
                #pragma unroll
                for (int nt = 0; nt < 4; nt++)
                    mma_bf16(acc[mt][nt], al[mt], bh[nt]);
        }
    }

    // epilogue
    int g = lane >> 2, tig = lane & 3;
    #pragma unroll
    for (int mt = 0; mt < 4; mt++) {
        int row0 = bm + warp_m*64 + mt*16 + g;
        #pragma unroll
        for (int nt = 0; nt < 4; nt++) {
            int col = bn + warp_n*32 + nt*8 + tig*2;
            if (col < N) {
                #pragma unroll
                for (int h = 0; h < 2; h++) {
                    int row = row0 + h*8;
                    float v0 = acc[mt][nt][h*2+0];
                    float v1 = acc[mt][nt][h*2+1];
                    size_t idx = (size_t)row * N + col;
                    if (EPI == 1) { v0 += add[idx]; v1 += add[idx+1]; }
                    if (EPI == 3) { v0 += bias[col] + add[idx]; v1 += bias[col+1] + add[idx+1]; }
                    if (EPI == 2) {
                        v0 += bias[col];   v0 = 0.5f*v0*(1.f + erff(v0*0.70710678118f));
                        v1 += bias[col+1]; v1 = 0.5f*v1*(1.f + erff(v1*0.70710678118f));
                        __nv_bfloat16 h0,h1,l0,l1;
                        split1(v0,h0,l0); split1(v1,h1,l1);
                        __nv_bfloat162 hp = __halves2bfloat162(h0,h1);
                        __nv_bfloat162 lp = __halves2bfloat162(l0,l1);
                        *(uint32_t*)(Ohi + idx) = *(uint32_t*)&hp;
                        *(uint32_t*)(Olo + idx) = *(uint32_t*)&lp;
                    } else {
                        *(float2*)(C + idx) = make_float2(v0, v1);
                    }
                }
            }
        }
    }
}

// ---------------- conv1d(width4, causal) + SiLU + dt softplus ----------------
__global__ void conv_kernel(const float* __restrict__ conv_w, const float* __restrict__ conv_b,
                            const float* __restrict__ dt_bias)
{
    int r = blockIdx.x;
    int b = r >> 11, l = r & (LSEQ-1);
    for (int c = threadIdx.x; c < CONVDIM; c += 256) {
        float acc = conv_b[c];
        #pragma unroll
        for (int k = 0; k < 4; k++) {
            int ll = l + k - 3;
            if (ll >= 0)
                acc = fmaf(g_zx[(size_t)(b*LSEQ + ll)*DINPROJ + DI + c], conv_w[c*4 + k], acc);
        }
        acc = acc / (1.f + expf(-acc));   // SiLU
        g_xbc[(size_t)r*CONVDIM + c] = acc;
    }
    if (threadIdx.x < NH) {
        int hh = threadIdx.x;
        float raw = g_zx[(size_t)r*DINPROJ + DI + CONVDIM + hh] + dt_bias[hh];
        g_dt[r*NH + hh] = (raw > 20.f) ? raw : log1pf(expf(raw));
    }
}

// ---------------- selective scan: one block per (batch, head) ----------------
__global__ void __launch_bounds__(256) scan_kernel(const float* __restrict__ A_log,
                                                   const float* __restrict__ Dvec)
{
    int bh = blockIdx.x;
    int b = bh >> 5, h = bh & 31;
    int t = threadIdx.x;
    int p = t >> 2, nq = t & 3;

    float A_h = -expf(A_log[h]);
    float Dh  = Dvec[h];

    __shared__ float sX[2][64], sB[2][64], sC[2][64];
    __shared__ float sdt[2];

    const size_t base0 = (size_t)(b*LSEQ)*CONVDIM;
    auto load = [&](int buf, int l) {
        size_t rb = base0 + (size_t)l*CONVDIM;
        if (t < 64)        sX[buf][t]       = g_xbc[rb + h*HD + t];
        else if (t < 128)  sB[buf][t-64]    = g_xbc[rb + DI + (t-64)];
        else if (t < 192)  sC[buf][t-128]   = g_xbc[rb + DI + DSTATE + (t-128)];
        else if (t == 192) sdt[buf]         = g_dt[(b*LSEQ + l)*NH + h];
    };

    load(0, 0);
    __syncthreads();

    float st[16];
    #pragma unroll
    for (int i = 0; i < 16; i++) st[i] = 0.f;

    for (int l = 0; l < LSEQ; l++) {
        int buf = l & 1;
        if (l + 1 < LSEQ) load(buf ^ 1, l + 1);

        float dtv  = sdt[buf];
        float dA   = expf(dtv * A_h);
        float xv   = sX[buf][p];
        float coef = dtv * xv;

        const float* Bp = &sB[buf][nq*16];
        const float* Cp = &sC[buf][nq*16];
        float acc = 0.f;
        #pragma unroll
        for (int i = 0; i < 16; i++) {
            float s2 = fmaf(st[i], dA, coef * Bp[i]);
            st[i] = s2;
            acc = fmaf(s2, Cp[i], acc);
        }
        acc += __shfl_xor_sync(0xffffffffu, acc, 1);
        acc += __shfl_xor_sync(0xffffffffu, acc, 2);
        if (nq == 0)
            g_y[(size_t)(b*LSEQ + l)*DI + h*HD + p] = acc + xv * Dh;
        __syncthreads();
    }
}

// ---------------- gate (y * silu(z)) + RMSNorm + split (bf16 hi/lo out) ----------------
__global__ void gate_rms_split_kernel(const float* __restrict__ norm_w,
                                      __nv_bfloat16* __restrict__ hi,
                                      __nv_bfloat16* __restrict__ lo)
{
    int r = blockIdx.x;
    size_t zb = (size_t)r*DINPROJ;
    size_t yb = (size_t)r*DI;
    int c0 = threadIdx.x * 8;

    float v[8];
    float ss = 0.f;
    #pragma unroll
    for (int q = 0; q < 2; q++) {
        float4 yv = *(const float4*)(g_y + yb + c0 + q*4);
        float4 zv = *(const float4*)(g_zx + zb + c0 + q*4);
        float* vv = v + q*4;
        vv[0] = yv.x * (zv.x / (1.f + expf(-zv.x)));
        vv[1] = yv.y * (zv.y / (1.f + expf(-zv.y)));
        vv[2] = yv.z * (zv.z / (1.f + expf(-zv.z)));
        vv[3] = yv.w * (zv.w / (1.f + expf(-zv.w)));
        ss += vv[0]*vv[0] + vv[1]*vv[1] + vv[2]*vv[2] + vv[3]*vv[3];
    }
    __shared__ float red[8];
    #pragma unroll
    for (int o = 16; o; o >>= 1) ss += __shfl_xor_sync(0xffffffffu, ss, o);
    if ((threadIdx.x & 31) == 0) red[threadIdx.x >> 5] = ss;
    __syncthreads();
    ss = 0.f;
    #pragma unroll
    for (int i = 0; i < 8; i++) ss += red[i];
    float sc = rsqrtf(ss * (1.f/DI) + EPSF);

    uint32_t hp[4], lp[4];
    #pragma unroll
    for (int q = 0; q < 4; q++) {
        float o0 = v[q*2+0] * sc * norm_w[c0 + q*2+0];
        float o1 = v[q*2+1] * sc * norm_w[c0 + q*2+1];
        __nv_bfloat16 h0,h1,l0,l1;
        split1(o0,h0,l0); split1(o1,h1,l1);
        __nv_bfloat162 hv = __halves2bfloat162(h0,h1);
        __nv_bfloat162 lv = __halves2bfloat162(l0,l1);
        hp[q] = *(uint32_t*)&hv; lp[q] = *(uint32_t*)&lv;
    }
    *(uint4*)(hi + yb + c0) = make_uint4(hp[0],hp[1],hp[2],hp[3]);
    *(uint4*)(lo + yb + c0) = make_uint4(lp[0],lp[1],lp[2],lp[3]);
}

// ---------------- launch ----------------
extern "C" void kernel_launch(void* const* d_in, const int* in_sizes, int n_in,
                              void* d_out, int out_size)
{
    const float* x          = (const float*)d_in[0];
    const float* ln1_w      = (const float*)d_in[1];
    const float* ln1_b      = (const float*)d_in[2];
    const float* in_proj_w  = (const float*)d_in[3];
    const float* conv_w     = (const float*)d_in[4];
    const float* conv_b     = (const float*)d_in[5];
    const float* dt_bias    = (const float*)d_in[6];
    const float* A_log      = (const float*)d_in[7];
    const float* Dvec       = (const float*)d_in[8];
    const float* norm_w     = (const float*)d_in[9];
    const float* out_proj_w = (const float*)d_in[10];
    const float* ln2_w      = (const float*)d_in[11];
    const float* ln2_b      = (const float*)d_in[12];
    const float* mlp_w1     = (const float*)d_in[13];
    const float* mlp_b1     = (const float*)d_in[14];
    const float* mlp_w2     = (const float*)d_in[15];
    const float* mlp_b2     = (const float*)d_in[16];
    float* out = (float*)d_out;

    float *zxp, *yp, *x1p;
    cudaGetSymbolAddress((void**)&zxp,  g_zx);
    cudaGetSymbolAddress((void**)&yp,   g_y);
    cudaGetSymbolAddress((void**)&x1p,  g_x1);

    __nv_bfloat16 *wip_h, *wip_l, *wop_h, *wop_l, *wm1_h, *wm1_l, *wm2_h, *wm2_l;
    __nv_bfloat16 *aln1_h, *aln1_l, *ay_h, *ay_l, *aln2_h, *aln2_l, *amlp_h, *amlp_l;
    cudaGetSymbolAddress((void**)&wip_h, w_ip_hi);  cudaGetSymbolAddress((void**)&wip_l, w_ip_lo);
    cudaGetSymbolAddress((void**)&wop_h, w_op_hi);  cudaGetSymbolAddress((void**)&wop_l, w_op_lo);
    cudaGetSymbolAddress((void**)&wm1_h, w_m1_hi);  cudaGetSymbolAddress((void**)&wm1_l, w_m1_lo);
    cudaGetSymbolAddress((void**)&wm2_h, w_m2_hi);  cudaGetSymbolAddress((void**)&wm2_l, w_m2_lo);
    cudaGetSymbolAddress((void**)&aln1_h, a_ln1_hi); cudaGetSymbolAddress((void**)&aln1_l, a_ln1_lo);
    cudaGetSymbolAddress((void**)&ay_h,  a_y_hi);   cudaGetSymbolAddress((void**)&ay_l,  a_y_lo);
    cudaGetSymbolAddress((void**)&aln2_h, a_ln2_hi); cudaGetSymbolAddress((void**)&aln2_l, a_ln2_lo);
    cudaGetSymbolAddress((void**)&amlp_h, a_mlp_hi); cudaGetSymbolAddress((void**)&amlp_l, a_mlp_lo);

    cudaFuncSetAttribute(gemm_tc<0>, cudaFuncAttributeMaxDynamicSharedMemorySize, GSMEM_BYTES);
    cudaFuncSetAttribute(gemm_tc<1>, cudaFuncAttributeMaxDynamicSharedMemorySize, GSMEM_BYTES);
    cudaFuncSetAttribute(gemm_tc<2>, cudaFuncAttributeMaxDynamicSharedMemorySize, GSMEM_BYTES);
    cudaFuncSetAttribute(gemm_tc<3>, cudaFuncAttributeMaxDynamicSharedMemorySize, GSMEM_BYTES);

    // weight splits
    cvt_kernel<<<512, 256>>>((const float4*)in_proj_w,  (uint2*)wip_h, (uint2*)wip_l, (size_t)DINPROJ*DM/4);
    cvt_kernel<<<512, 256>>>((const float4*)out_proj_w, (uint2*)wop_h, (uint2*)wop_l, (size_t)DM*DI/4);
    cvt_kernel<<<512, 256>>>((const float4*)mlp_w1,     (uint2*)wm1_h, (uint2*)wm1_l, (size_t)4*DM*DM/4);
    cvt_kernel<<<512, 256>>>((const float4*)mlp_w2,     (uint2*)wm2_h, (uint2*)wm2_l, (size_t)DM*4*DM/4);

    // 1. LN1 (fused split)
    ln_split_kernel<<<ROWS, 256>>>(x, ln1_w, ln1_b, aln1_h, aln1_l);
    // 2. zxbcdt = ln1 @ in_proj_w^T
    {
        dim3 g((DINPROJ + 127)/128, ROWS/128);
        gemm_tc<0><<<g, 256, GSMEM_BYTES>>>(aln1_h, aln1_l, wip_h, wip_l, zxp,
                                            ROWS, DINPROJ, DM, nullptr, nullptr, nullptr, nullptr);
    }
    // 3. conv + silu + dt softplus
    conv_kernel<<<ROWS, 256>>>(conv_w, conv_b, dt_bias);
    // 4. selective scan (+ D skip)
    scan_kernel<<<BATCH*NH, 256>>>(A_log, Dvec);
    // 5. gate + rmsnorm (fused split)
    gate_rms_split_kernel<<<ROWS, 256>>>(norm_w, ay_h, ay_l);
    // 6. x1 = x + y @ out_proj_w^T
    {
        dim3 g((DM + 127)/128, ROWS/128);
        gemm_tc<1><<<g, 256, GSMEM_BYTES>>>(ay_h, ay_l, wop_h, wop_l, x1p,
                                            ROWS, DM, DI, x, nullptr, nullptr, nullptr);
    }
    // 7. LN2 (fused split)
    ln_split_kernel<<<ROWS, 256>>>(x1p, ln2_w, ln2_b, aln2_h, aln2_l);
    // 8. mlp1 = gelu(ln2 @ mlp_w1^T + b1) -> bf16 hi/lo directly
    {
        dim3 g((4*DM + 127)/128, ROWS/128);
        gemm_tc<2><<<g, 256, GSMEM_BYTES>>>(aln2_h, aln2_l, wm1_h, wm1_l, nullptr,
                                            ROWS, 4*DM, DM, nullptr, mlp_b1, amlp_h, amlp_l);
    }
    // 9. out = x1 + mlp1 @ mlp_w2^T + b2
    {
        dim3 g((DM + 127)/128, ROWS/128);
        gemm_tc<3><<<g, 256, GSMEM_BYTES>>>(amlp_h, amlp_l, wm2_h, wm2_l, out,
                                            ROWS, DM, 4*DM, x1p, mlp_b2, nullptr, nullptr);
    }
}

// round 7
// speedup vs baseline: 1.4992x; 1.4992x over previous
#include <cuda_runtime.h>
#include <cuda_bf16.h>
#include <math.h>
#include <stdint.h>

#define BATCH   2
#define LSEQ    2048
#define DM      1024
#define DI      2048
#define DSTATE  64
#define HD      64
#define NH      32
#define CONVDIM 2176
#define DINPROJ 4256
#define ROWS    (BATCH*LSEQ)
#define EPSF    1e-5f

// ---------------- fp32 scratch ----------------
__device__ float g_zx [(size_t)ROWS*DINPROJ];
__device__ float g_xbc[(size_t)ROWS*CONVDIM];
__device__ float g_dt [(size_t)ROWS*NH];
__device__ float g_y  [(size_t)ROWS*DI];
__device__ float g_x1 [(size_t)ROWS*DM];

// ---------------- bf16 split scratch (hi/lo) ----------------
__device__ __nv_bfloat16 w_ip_hi[(size_t)DINPROJ*DM],  w_ip_lo[(size_t)DINPROJ*DM];
__device__ __nv_bfloat16 w_op_hi[(size_t)DM*DI],       w_op_lo[(size_t)DM*DI];
__device__ __nv_bfloat16 w_m1_hi[(size_t)4*DM*DM],     w_m1_lo[(size_t)4*DM*DM];
__device__ __nv_bfloat16 w_m2_hi[(size_t)DM*4*DM],     w_m2_lo[(size_t)DM*4*DM];
__device__ __nv_bfloat16 a_ln1_hi[(size_t)ROWS*DM],    a_ln1_lo[(size_t)ROWS*DM];
__device__ __nv_bfloat16 a_y_hi [(size_t)ROWS*DI],     a_y_lo [(size_t)ROWS*DI];
__device__ __nv_bfloat16 a_ln2_hi[(size_t)ROWS*DM],    a_ln2_lo[(size_t)ROWS*DM];
__device__ __nv_bfloat16 a_mlp_hi[(size_t)ROWS*4*DM],  a_mlp_lo[(size_t)ROWS*4*DM];

// ---------------- helpers ----------------
__device__ __forceinline__ uint32_t smem_u32(const void* p) {
    uint32_t a;
    asm("{ .reg .u64 t; cvta.to.shared.u64 t, %1; cvt.u32.u64 %0, t; }" : "=r"(a) : "l"(p));
    return a;
}
__device__ __forceinline__ void cp_async16(uint32_t saddr, const void* gaddr, uint32_t sz) {
    asm volatile("cp.async.cg.shared.global [%0], [%1], 16, %2;"
                 :: "r"(saddr), "l"(gaddr), "r"(sz));
}
__device__ __forceinline__ void cp_commit() { asm volatile("cp.async.commit_group;"); }
template<int N> __device__ __forceinline__ void cp_wait() {
    asm volatile("cp.async.wait_group %0;" :: "n"(N));
}
__device__ __forceinline__ void ldm_x4(uint32_t addr, uint32_t& r0, uint32_t& r1,
                                       uint32_t& r2, uint32_t& r3) {
    asm volatile("ldmatrix.sync.aligned.m8n8.x4.shared.b16 {%0,%1,%2,%3}, [%4];"
                 : "=r"(r0), "=r"(r1), "=r"(r2), "=r"(r3) : "r"(addr));
}
__device__ __forceinline__ void mma_bf16(float* c, const uint32_t* a, const uint32_t* b) {
    asm volatile(
        "mma.sync.aligned.m16n8k16.row.col.f32.bf16.bf16.f32 "
        "{%0,%1,%2,%3}, {%4,%5,%6,%7}, {%8,%9}, {%0,%1,%2,%3};"
        : "+f"(c[0]), "+f"(c[1]), "+f"(c[2]), "+f"(c[3])
        : "r"(a[0]), "r"(a[1]), "r"(a[2]), "r"(a[3]), "r"(b[0]), "r"(b[1]));
}
__device__ __forceinline__ void split1(float v, __nv_bfloat16& h, __nv_bfloat16& l) {
    h = __float2bfloat16(v);
    l = __float2bfloat16(v - __bfloat162float(h));
}

// ---------------- vectorized weight split ----------------
__global__ void cvt_kernel(const float4* __restrict__ in, uint2* __restrict__ hi,
                           uint2* __restrict__ lo, size_t n4)
{
    size_t i = (size_t)blockIdx.x * blockDim.x + threadIdx.x;
    size_t stride = (size_t)gridDim.x * blockDim.x;
    for (; i < n4; i += stride) {
        float4 v = in[i];
        __nv_bfloat16 h0,h1,h2,h3,l0,l1,l2,l3;
        split1(v.x,h0,l0); split1(v.y,h1,l1); split1(v.z,h2,l2); split1(v.w,h3,l3);
        __nv_bfloat162 hA = __halves2bfloat162(h0,h1), hB = __halves2bfloat162(h2,h3);
        __nv_bfloat162 lA = __halves2bfloat162(l0,l1), lB = __halves2bfloat162(l2,l3);
        hi[i] = make_uint2(*(uint32_t*)&hA, *(uint32_t*)&hB);
        lo[i] = make_uint2(*(uint32_t*)&lA, *(uint32_t*)&lB);
    }
}

// ---------------- layernorm + split (bf16 hi/lo out) ----------------
__global__ void ln_split_kernel(const float* __restrict__ in, const float* __restrict__ w,
                                const float* __restrict__ b,
                                __nv_bfloat16* __restrict__ hi, __nv_bfloat16* __restrict__ lo)
{
    int row = blockIdx.x;
    const float* x = in + (size_t)row*DM;
    int c0 = threadIdx.x * 4;
    float4 v = *(const float4*)(x + c0);
    float s  = v.x + v.y + v.z + v.w;
    float ss = v.x*v.x + v.y*v.y + v.z*v.z + v.w*v.w;
    __shared__ float red0[8], red1[8];
    #pragma unroll
    for (int o = 16; o; o >>= 1) {
        s  += __shfl_xor_sync(0xffffffffu, s, o);
        ss += __shfl_xor_sync(0xffffffffu, ss, o);
    }
    int warp = threadIdx.x >> 5, lane = threadIdx.x & 31;
    if (lane == 0) { red0[warp] = s; red1[warp] = ss; }
    __syncthreads();
    s = 0.f; ss = 0.f;
    #pragma unroll
    for (int i = 0; i < 8; i++) { s += red0[i]; ss += red1[i]; }
    float mu  = s * (1.f/DM);
    float var = ss * (1.f/DM) - mu*mu;
    float sc  = rsqrtf(var + EPSF);
    float4 wv = *(const float4*)(w + c0);
    float4 bv = *(const float4*)(b + c0);
    float o0 = (v.x-mu)*sc*wv.x + bv.x;
    float o1 = (v.y-mu)*sc*wv.y + bv.y;
    float o2 = (v.z-mu)*sc*wv.z + bv.z;
    float o3 = (v.w-mu)*sc*wv.w + bv.w;
    __nv_bfloat16 h0,h1,h2,h3,l0,l1,l2,l3;
    split1(o0,h0,l0); split1(o1,h1,l1); split1(o2,h2,l2); split1(o3,h3,l3);
    __nv_bfloat162 hA = __halves2bfloat162(h0,h1), hB = __halves2bfloat162(h2,h3);
    __nv_bfloat162 lA = __halves2bfloat162(l0,l1), lB = __halves2bfloat162(l2,l3);
    size_t ob = (size_t)row*DM + c0;
    *(uint2*)(hi + ob) = make_uint2(*(uint32_t*)&hA, *(uint32_t*)&hB);
    *(uint2*)(lo + ob) = make_uint2(*(uint32_t*)&lA, *(uint32_t*)&lB);
}

// ---------------- HMMA split-bf16 GEMM: C[M,N] = A[M,K] @ B[N,K]^T ----------------
// 128x128 tile, BK=32, 3-stage cp.async pipeline, one barrier per k-chunk.
// MMA ordering: mt-outer / term-mid / nt-inner -> distance-4 between dependent MMAs,
// identical register live ranges to the R5 interleaved version.
// EPI: 0=plain fp32, 1=fp32+add, 2=bias+gelu -> bf16 hi/lo split out, 3=fp32+bias+add
#define PITCHB   80
#define MATB     (128*PITCHB)
#define STAGEB   (4*MATB)        // 40960
#define NSTAGE   3
#define GSMEM_BYTES (NSTAGE*STAGEB)  // 122880

template<int EPI>
__global__ void __launch_bounds__(256, 1)
gemm_tc(const __nv_bfloat16* __restrict__ Ahi, const __nv_bfloat16* __restrict__ Alo,
        const __nv_bfloat16* __restrict__ Bhi, const __nv_bfloat16* __restrict__ Blo,
        float* __restrict__ C, int M, int N, int K,
        const float* __restrict__ add, const float* __restrict__ bias,
        __nv_bfloat16* __restrict__ Ohi, __nv_bfloat16* __restrict__ Olo)
{
    extern __shared__ __align__(128) char smem[];
    uint32_t sb = smem_u32(smem);
    int tid = threadIdx.x, wid = tid >> 5, lane = tid & 31;
    int bm = blockIdx.y * 128, bn = blockIdx.x * 128;
    int warp_m = wid >> 2, warp_n = wid & 3;
    int nrow_b = N - bn;

    int lr0 = tid >> 2, lc0 = (tid & 3);
    int lr1 = (tid + 256) >> 2, lc1 = (tid & 3);

    const int NK = K >> 5;

    auto issue_load = [&](int kc) {
        uint32_t s0 = sb + (kc % NSTAGE) * STAGEB;
        int k0 = kc << 5;
        {
            size_t ga0 = (size_t)(bm + lr0) * K + k0 + lc0 * 8;
            size_t ga1 = (size_t)(bm + lr1) * K + k0 + lc1 * 8;
            cp_async16(s0 + 0*MATB + lr0*PITCHB + lc0*16, Ahi + ga0, 16);
            cp_async16(s0 + 0*MATB + lr1*PITCHB + lc1*16, Ahi + ga1, 16);
            cp_async16(s0 + 1*MATB + lr0*PITCHB + lc0*16, Alo + ga0, 16);
            cp_async16(s0 + 1*MATB + lr1*PITCHB + lc1*16, Alo + ga1, 16);
        }
        {
            int r0 = lr0 < nrow_b ? lr0 : 0;  uint32_t z0 = lr0 < nrow_b ? 16u : 0u;
            int r1 = lr1 < nrow_b ? lr1 : 0;  uint32_t z1 = lr1 < nrow_b ? 16u : 0u;
            size_t gb0 = (size_t)(bn + r0) * K + k0 + lc0 * 8;
            size_t gb1 = (size_t)(bn + r1) * K + k0 + lc1 * 8;
            cp_async16(s0 + 2*MATB + lr0*PITCHB + lc0*16, Bhi + gb0, z0);
            cp_async16(s0 + 2*MATB + lr1*PITCHB + lc1*16, Bhi + gb1, z1);
            cp_async16(s0 + 3*MATB + lr0*PITCHB + lc0*16, Blo + gb0, z0);
            cp_async16(s0 + 3*MATB + lr1*PITCHB + lc1*16, Blo + gb1, z1);
        }
        cp_commit();
    };

    float acc[4][4][4];
    #pragma unroll
    for (int i = 0; i < 4; i++)
        #pragma unroll
        for (int j = 0; j < 4; j++)
            #pragma unroll
            for (int q = 0; q < 4; q++) acc[i][j][q] = 0.f;

    issue_load(0);
    if (NK > 1) issue_load(1);

    int a_row = warp_m * 64 + (lane & 15);
    int a_colb = ((lane >> 4) << 3) * 2;
    int b_row = warp_n * 32 + ((lane >> 4) << 3) + (lane & 7);
    int b_colb = (((lane >> 3) & 1) << 3) * 2;

    for (int kc = 0; kc < NK; kc++) {
        uint32_t s0 = sb + (kc % NSTAGE) * STAGEB;
        if (kc + 1 < NK) cp_wait<1>(); else cp_wait<0>();
        __syncthreads();
        if (kc + 2 < NK) issue_load(kc + 2);

        #pragma unroll
        for (int ks = 0; ks < 2; ks++) {
            uint32_t ah[4][4], al[4][4], bh[4][2], bl[4][2];
            #pragma unroll
            for (int mt = 0; mt < 4; mt++) {
                uint32_t ad = s0 + 0*MATB + (a_row + mt*16)*PITCHB + a_colb + ks*32;
                ldm_x4(ad, ah[mt][0], ah[mt][1], ah[mt][2], ah[mt][3]);
                ldm_x4(ad + MATB, al[mt][0], al[mt][1], al[mt][2], al[mt][3]);
            }
            #pragma unroll
            for (int nh = 0; nh < 2; nh++) {
                uint32_t bd = s0 + 2*MATB + (b_row + nh*16)*PITCHB + b_colb + ks*32;
                ldm_x4(bd, bh[nh*2][0], bh[nh*2][1], bh[nh*2+1][0], bh[nh*2+1][1]);
                ldm_x4(bd + MATB, bl[nh*2][0], bl[nh*2][1], bl[nh*2+1][0], bl[nh*2+1][1]);
            }
            // mt-outer / term-mid / nt-inner: dependent MMAs 4 apart
            #pragma unroll
            for (int mt = 0; mt < 4; mt++) {
                #pragma unroll
                for (int nt = 0; nt < 4; nt++)
                    mma_bf16(acc[mt][nt], ah[mt], bh[nt]);
                #pragma unroll
                for (int nt = 0; nt < 4; nt++)
                    mma_bf16(acc[mt][nt], ah[mt], bl[nt]);
                #pragma unroll
                for (int nt = 0; nt < 4; nt++)
                    mma_bf16(acc[mt][nt], al[mt], bh[nt]);
            }
        }
    }

    // epilogue
    int g = lane >> 2, tig = lane & 3;
    #pragma unroll
    for (int mt = 0; mt < 4; mt++) {
        int row0 = bm + warp_m*64 + mt*16 + g;
        #pragma unroll
        for (int nt = 0; nt < 4; nt++) {
            int col = bn + warp_n*32 + nt*8 + tig*2;
            if (col < N) {
                #pragma unroll
                for (int h = 0; h < 2; h++) {
                    int row = row0 + h*8;
                    float v0 = acc[mt][nt][h*2+0];
                    float v1 = acc[mt][nt][h*2+1];
                    size_t idx = (size_t)row * N + col;
                    if (EPI == 1) { v0 += add[idx]; v1 += add[idx+1]; }
                    if (EPI == 3) { v0 += bias[col] + add[idx]; v1 += bias[col+1] + add[idx+1]; }
                    if (EPI == 2) {
                        v0 += bias[col];   v0 = 0.5f*v0*(1.f + erff(v0*0.70710678118f));
                        v1 += bias[col+1]; v1 = 0.5f*v1*(1.f + erff(v1*0.70710678118f));
                        __nv_bfloat16 h0,h1,l0,l1;
                        split1(v0,h0,l0); split1(v1,h1,l1);
                        __nv_bfloat162 hp = __halves2bfloat162(h0,h1);
                        __nv_bfloat162 lp = __halves2bfloat162(l0,l1);
                        *(uint32_t*)(Ohi + idx) = *(uint32_t*)&hp;
                        *(uint32_t*)(Olo + idx) = *(uint32_t*)&lp;
                    } else {
                        *(float2*)(C + idx) = make_float2(v0, v1);
                    }
                }
            }
        }
    }
}

// ---------------- conv1d(width4, causal) + SiLU + dt softplus ----------------
__global__ void conv_kernel(const float* __restrict__ conv_w, const float* __restrict__ conv_b,
                            const float* __restrict__ dt_bias)
{
    int r = blockIdx.x;
    int b = r >> 11, l = r & (LSEQ-1);
    for (int c = threadIdx.x; c < CONVDIM; c += 256) {
        float acc = conv_b[c];
        #pragma unroll
        for (int k = 0; k < 4; k++) {
            int ll = l + k - 3;
            if (ll >= 0)
                acc = fmaf(g_zx[(size_t)(b*LSEQ + ll)*DINPROJ + DI + c], conv_w[c*4 + k], acc);
        }
        acc = acc / (1.f + expf(-acc));   // SiLU
        g_xbc[(size_t)r*CONVDIM + c] = acc;
    }
    if (threadIdx.x < NH) {
        int hh = threadIdx.x;
        float raw = g_zx[(size_t)r*DINPROJ + DI + CONVDIM + hh] + dt_bias[hh];
        g_dt[r*NH + hh] = (raw > 20.f) ? raw : log1pf(expf(raw));
    }
}

// ---------------- selective scan: one block per (batch, head) ----------------
__global__ void __launch_bounds__(256) scan_kernel(const float* __restrict__ A_log,
                                                   const float* __restrict__ Dvec)
{
    int bh = blockIdx.x;
    int b = bh >> 5, h = bh & 31;
    int t = threadIdx.x;
    int p = t >> 2, nq = t & 3;

    float A_h = -expf(A_log[h]);
    float Dh  = Dvec[h];

    __shared__ float sX[2][64], sB[2][64], sC[2][64];
    __shared__ float sdt[2];

    const size_t base0 = (size_t)(b*LSEQ)*CONVDIM;
    auto load = [&](int buf, int l) {
        size_t rb = base0 + (size_t)l*CONVDIM;
        if (t < 64)        sX[buf][t]       = g_xbc[rb + h*HD + t];
        else if (t < 128)  sB[buf][t-64]    = g_xbc[rb + DI + (t-64)];
        else if (t < 192)  sC[buf][t-128]   = g_xbc[rb + DI + DSTATE + (t-128)];
        else if (t == 192) sdt[buf]         = g_dt[(b*LSEQ + l)*NH + h];
    };

    load(0, 0);
    __syncthreads();

    float st[16];
    #pragma unroll
    for (int i = 0; i < 16; i++) st[i] = 0.f;

    for (int l = 0; l < LSEQ; l++) {
        int buf = l & 1;
        if (l + 1 < LSEQ) load(buf ^ 1, l + 1);

        float dtv  = sdt[buf];
        float dA   = expf(dtv * A_h);
        float xv   = sX[buf][p];
        float coef = dtv * xv;

        const float* Bp = &sB[buf][nq*16];
        const float* Cp = &sC[buf][nq*16];
        float acc = 0.f;
        #pragma unroll
        for (int i = 0; i < 16; i++) {
            float s2 = fmaf(st[i], dA, coef * Bp[i]);
            st[i] = s2;
            acc = fmaf(s2, Cp[i], acc);
        }
        acc += __shfl_xor_sync(0xffffffffu, acc, 1);
        acc += __shfl_xor_sync(0xffffffffu, acc, 2);
        if (nq == 0)
            g_y[(size_t)(b*LSEQ + l)*DI + h*HD + p] = acc + xv * Dh;
        __syncthreads();
    }
}

// ---------------- gate (y * silu(z)) + RMSNorm + split (bf16 hi/lo out) ----------------
__global__ void gate_rms_split_kernel(const float* __restrict__ norm_w,
                                      __nv_bfloat16* __restrict__ hi,
                                      __nv_bfloat16* __restrict__ lo)
{
    int r = blockIdx.x;
    size_t zb = (size_t)r*DINPROJ;
    size_t yb = (size_t)r*DI;
    int c0 = threadIdx.x * 8;

    float v[8];
    float ss = 0.f;
    #pragma unroll
    for (int q = 0; q < 2; q++) {
        float4 yv = *(const float4*)(g_y + yb + c0 + q*4);
        float4 zv = *(const float4*)(g_zx + zb + c0 + q*4);
        float* vv = v + q*4;
        vv[0] = yv.x * (zv.x / (1.f + expf(-zv.x)));
        vv[1] = yv.y * (zv.y / (1.f + expf(-zv.y)));
        vv[2] = yv.z * (zv.z / (1.f + expf(-zv.z)));
        vv[3] = yv.w * (zv.w / (1.f + expf(-zv.w)));
        ss += vv[0]*vv[0] + vv[1]*vv[1] + vv[2]*vv[2] + vv[3]*vv[3];
    }
    __shared__ float red[8];
    #pragma unroll
    for (int o = 16; o; o >>= 1) ss += __shfl_xor_sync(0xffffffffu, ss, o);
    if ((threadIdx.x & 31) == 0) red[threadIdx.x >> 5] = ss;
    __syncthreads();
    ss = 0.f;
    #pragma unroll
    for (int i = 0; i < 8; i++) ss += red[i];
    float sc = rsqrtf(ss * (1.f/DI) + EPSF);

    uint32_t hp[4], lp[4];
    #pragma unroll
    for (int q = 0; q < 4; q++) {
        float o0 = v[q*2+0] * sc * norm_w[c0 + q*2+0];
        float o1 = v[q*2+1] * sc * norm_w[c0 + q*2+1];
        __nv_bfloat16 h0,h1,l0,l1;
        split1(o0,h0,l0); split1(o1,h1,l1);
        __nv_bfloat162 hv = __halves2bfloat162(h0,h1);
        __nv_bfloat162 lv = __halves2bfloat162(l0,l1);
        hp[q] = *(uint32_t*)&hv; lp[q] = *(uint32_t*)&lv;
    }
    *(uint4*)(hi + yb + c0) = make_uint4(hp[0],hp[1],hp[2],hp[3]);
    *(uint4*)(lo + yb + c0) = make_uint4(lp[0],lp[1],lp[2],lp[3]);
}

// ---------------- launch ----------------
extern "C" void kernel_launch(void* const* d_in, const int* in_sizes, int n_in,
                              void* d_out, int out_size)
{
    const float* x          = (const float*)d_in[0];
    const float* ln1_w      = (const float*)d_in[1];
    const float* ln1_b      = (const float*)d_in[2];
    const float* in_proj_w  = (const float*)d_in[3];
    const float* conv_w     = (const float*)d_in[4];
    const float* conv_b     = (const float*)d_in[5];
    const float* dt_bias    = (const float*)d_in[6];
    const float* A_log      = (const float*)d_in[7];
    const float* Dvec       = (const float*)d_in[8];
    const float* norm_w     = (const float*)d_in[9];
    const float* out_proj_w = (const float*)d_in[10];
    const float* ln2_w      = (const float*)d_in[11];
    const float* ln2_b      = (const float*)d_in[12];
    const float* mlp_w1     = (const float*)d_in[13];
    const float* mlp_b1     = (const float*)d_in[14];
    const float* mlp_w2     = (const float*)d_in[15];
    const float* mlp_b2     = (const float*)d_in[16];
    float* out = (float*)d_out;

    float *zxp, *yp, *x1p;
    cudaGetSymbolAddress((void**)&zxp,  g_zx);
    cudaGetSymbolAddress((void**)&yp,   g_y);
    cudaGetSymbolAddress((void**)&x1p,  g_x1);

    __nv_bfloat16 *wip_h, *wip_l, *wop_h, *wop_l, *wm1_h, *wm1_l, *wm2_h, *wm2_l;
    __nv_bfloat16 *aln1_h, *aln1_l, *ay_h, *ay_l, *aln2_h, *aln2_l, *amlp_h, *amlp_l;
    cudaGetSymbolAddress((void**)&wip_h, w_ip_hi);  cudaGetSymbolAddress((void**)&wip_l, w_ip_lo);
    cudaGetSymbolAddress((void**)&wop_h, w_op_hi);  cudaGetSymbolAddress((void**)&wop_l, w_op_lo);
    cudaGetSymbolAddress((void**)&wm1_h, w_m1_hi);  cudaGetSymbolAddress((void**)&wm1_l, w_m1_lo);
    cudaGetSymbolAddress((void**)&wm2_h, w_m2_hi);  cudaGetSymbolAddress((void**)&wm2_l, w_m2_lo);
    cudaGetSymbolAddress((void**)&aln1_h, a_ln1_hi); cudaGetSymbolAddress((void**)&aln1_l, a_ln1_lo);
    cudaGetSymbolAddress((void**)&ay_h,  a_y_hi);   cudaGetSymbolAddress((void**)&ay_l,  a_y_lo);
    cudaGetSymbolAddress((void**)&aln2_h, a_ln2_hi); cudaGetSymbolAddress((void**)&aln2_l, a_ln2_lo);
    cudaGetSymbolAddress((void**)&amlp_h, a_mlp_hi); cudaGetSymbolAddress((void**)&amlp_l, a_mlp_lo);

    cudaFuncSetAttribute(gemm_tc<0>, cudaFuncAttributeMaxDynamicSharedMemorySize, GSMEM_BYTES);
    cudaFuncSetAttribute(gemm_tc<1>, cudaFuncAttributeMaxDynamicSharedMemorySize, GSMEM_BYTES);
    cudaFuncSetAttribute(gemm_tc<2>, cudaFuncAttributeMaxDynamicSharedMemorySize, GSMEM_BYTES);
    cudaFuncSetAttribute(gemm_tc<3>, cudaFuncAttributeMaxDynamicSharedMemorySize, GSMEM_BYTES);

    // weight splits
    cvt_kernel<<<512, 256>>>((const float4*)in_proj_w,  (uint2*)wip_h, (uint2*)wip_l, (size_t)DINPROJ*DM/4);
    cvt_kernel<<<512, 256>>>((const float4*)out_proj_w, (uint2*)wop_h, (uint2*)wop_l, (size_t)DM*DI/4);
    cvt_kernel<<<512, 256>>>((const float4*)mlp_w1,     (uint2*)wm1_h, (uint2*)wm1_l, (size_t)4*DM*DM/4);
    cvt_kernel<<<512, 256>>>((const float4*)mlp_w2,     (uint2*)wm2_h, (uint2*)wm2_l, (size_t)DM*4*DM/4);

    // 1. LN1 (fused split)
    ln_split_kernel<<<ROWS, 256>>>(x, ln1_w, ln1_b, aln1_h, aln1_l);
    // 2. zxbcdt = ln1 @ in_proj_w^T
    {
        dim3 g((DINPROJ + 127)/128, ROWS/128);
        gemm_tc<0><<<g, 256, GSMEM_BYTES>>>(aln1_h, aln1_l, wip_h, wip_l, zxp,
                                            ROWS, DINPROJ, DM, nullptr, nullptr, nullptr, nullptr);
    }
    // 3. conv + silu + dt softplus
    conv_kernel<<<ROWS, 256>>>(conv_w, conv_b, dt_bias);
    // 4. selective scan (+ D skip)
    scan_kernel<<<BATCH*NH, 256>>>(A_log, Dvec);
    // 5. gate + rmsnorm (fused split)
    gate_rms_split_kernel<<<ROWS, 256>>>(norm_w, ay_h, ay_l);
    // 6. x1 = x + y @ out_proj_w^T
    {
        dim3 g((DM + 127)/128, ROWS/128);
        gemm_tc<1><<<g, 256, GSMEM_BYTES>>>(ay_h, ay_l, wop_h, wop_l, x1p,
                                            ROWS, DM, DI, x, nullptr, nullptr, nullptr);
    }
    // 7. LN2 (fused split)
    ln_split_kernel<<<ROWS, 256>>>(x1p, ln2_w, ln2_b, aln2_h, aln2_l);
    // 8. mlp1 = gelu(ln2 @ mlp_w1^T + b1) -> bf16 hi/lo directly
    {
        dim3 g((4*DM + 127)/128, ROWS/128);
        gemm_tc<2><<<g, 256, GSMEM_BYTES>>>(aln2_h, aln2_l, wm1_h, wm1_l, nullptr,
                                            ROWS, 4*DM, DM, nullptr, mlp_b1, amlp_h, amlp_l);
    }
    // 9. out = x1 + mlp1 @ mlp_w2^T + b2
    {
        dim3 g((DM + 127)/128, ROWS/128);
        gemm_tc<3><<<g, 256, GSMEM_BYTES>>>(amlp_h, amlp_l, wm2_h, wm2_l, out,
                                            ROWS, DM, 4*DM, x1p, mlp_b2, nullptr, nullptr);
    }
}

// round 8
// speedup vs baseline: 1.7424x; 1.1622x over previous
#include <cuda_runtime.h>
#include <cuda_fp16.h>
#include <math.h>
#include <stdint.h>

#define BATCH   2
#define LSEQ    2048
#define DM      1024
#define DI      2048
#define DSTATE  64
#define HD      64
#define NH      32
#define CONVDIM 2176
#define DINPROJ 4256
#define ROWS    (BATCH*LSEQ)
#define EPSF    1e-5f

// ---------------- fp32 scratch ----------------
__device__ float g_zx [(size_t)ROWS*DINPROJ];
__device__ float g_xbc[(size_t)ROWS*CONVDIM];
__device__ float g_dt [(size_t)ROWS*NH];
__device__ float g_y  [(size_t)ROWS*DI];
__device__ float g_x1 [(size_t)ROWS*DM];

// ---------------- fp16 scratch: weights split hi/lo, activations single ----------------
__device__ __half w_ip_hi[(size_t)DINPROJ*DM],  w_ip_lo[(size_t)DINPROJ*DM];
__device__ __half w_op_hi[(size_t)DM*DI],       w_op_lo[(size_t)DM*DI];
__device__ __half w_m1_hi[(size_t)4*DM*DM],     w_m1_lo[(size_t)4*DM*DM];
__device__ __half w_m2_hi[(size_t)DM*4*DM],     w_m2_lo[(size_t)DM*4*DM];
__device__ __half a_ln1[(size_t)ROWS*DM];
__device__ __half a_y  [(size_t)ROWS*DI];
__device__ __half a_ln2[(size_t)ROWS*DM];
__device__ __half a_mlp[(size_t)ROWS*4*DM];

// ---------------- helpers ----------------
__device__ __forceinline__ uint32_t smem_u32(const void* p) {
    uint32_t a;
    asm("{ .reg .u64 t; cvta.to.shared.u64 t, %1; cvt.u32.u64 %0, t; }" : "=r"(a) : "l"(p));
    return a;
}
__device__ __forceinline__ void cp_async16(uint32_t saddr, const void* gaddr, uint32_t sz) {
    asm volatile("cp.async.cg.shared.global [%0], [%1], 16, %2;"
                 :: "r"(saddr), "l"(gaddr), "r"(sz));
}
__device__ __forceinline__ void cp_commit() { asm volatile("cp.async.commit_group;"); }
template<int N> __device__ __forceinline__ void cp_wait() {
    asm volatile("cp.async.wait_group %0;" :: "n"(N));
}
__device__ __forceinline__ void ldm_x4(uint32_t addr, uint32_t& r0, uint32_t& r1,
                                       uint32_t& r2, uint32_t& r3) {
    asm volatile("ldmatrix.sync.aligned.m8n8.x4.shared.b16 {%0,%1,%2,%3}, [%4];"
                 : "=r"(r0), "=r"(r1), "=r"(r2), "=r"(r3) : "r"(addr));
}
__device__ __forceinline__ void mma_f16(float* c, const uint32_t* a, const uint32_t* b) {
    asm volatile(
        "mma.sync.aligned.m16n8k16.row.col.f32.f16.f16.f32 "
        "{%0,%1,%2,%3}, {%4,%5,%6,%7}, {%8,%9}, {%0,%1,%2,%3};"
        : "+f"(c[0]), "+f"(c[1]), "+f"(c[2]), "+f"(c[3])
        : "r"(a[0]), "r"(a[1]), "r"(a[2]), "r"(a[3]), "r"(b[0]), "r"(b[1]));
}
__device__ __forceinline__ void splith(float v, __half& h, __half& l) {
    h = __float2half(v);
    l = __float2half(v - __half2float(h));
}

// ---------------- vectorized weight split (fp16 hi/lo) ----------------
__global__ void cvt_kernel(const float4* __restrict__ in, uint2* __restrict__ hi,
                           uint2* __restrict__ lo, size_t n4)
{
    size_t i = (size_t)blockIdx.x * blockDim.x + threadIdx.x;
    size_t stride = (size_t)gridDim.x * blockDim.x;
    for (; i < n4; i += stride) {
        float4 v = in[i];
        __half h0,h1,h2,h3,l0,l1,l2,l3;
        splith(v.x,h0,l0); splith(v.y,h1,l1); splith(v.z,h2,l2); splith(v.w,h3,l3);
        __half2 hA = __halves2half2(h0,h1), hB = __halves2half2(h2,h3);
        __half2 lA = __halves2half2(l0,l1), lB = __halves2half2(l2,l3);
        hi[i] = make_uint2(*(uint32_t*)&hA, *(uint32_t*)&hB);
        lo[i] = make_uint2(*(uint32_t*)&lA, *(uint32_t*)&lB);
    }
}

// ---------------- layernorm -> fp16 out ----------------
__global__ void ln_h_kernel(const float* __restrict__ in, const float* __restrict__ w,
                            const float* __restrict__ b, __half* __restrict__ outh)
{
    int row = blockIdx.x;
    const float* x = in + (size_t)row*DM;
    int c0 = threadIdx.x * 4;
    float4 v = *(const float4*)(x + c0);
    float s  = v.x + v.y + v.z + v.w;
    float ss = v.x*v.x + v.y*v.y + v.z*v.z + v.w*v.w;
    __shared__ float red0[8], red1[8];
    #pragma unroll
    for (int o = 16; o; o >>= 1) {
        s  += __shfl_xor_sync(0xffffffffu, s, o);
        ss += __shfl_xor_sync(0xffffffffu, ss, o);
    }
    int warp = threadIdx.x >> 5, lane = threadIdx.x & 31;
    if (lane == 0) { red0[warp] = s; red1[warp] = ss; }
    __syncthreads();
    s = 0.f; ss = 0.f;
    #pragma unroll
    for (int i = 0; i < 8; i++) { s += red0[i]; ss += red1[i]; }
    float mu  = s * (1.f/DM);
    float var = ss * (1.f/DM) - mu*mu;
    float sc  = rsqrtf(var + EPSF);
    float4 wv = *(const float4*)(w + c0);
    float4 bv = *(const float4*)(b + c0);
    __half2 pA = __halves2half2(__float2half((v.x-mu)*sc*wv.x + bv.x),
                                __float2half((v.y-mu)*sc*wv.y + bv.y));
    __half2 pB = __halves2half2(__float2half((v.z-mu)*sc*wv.z + bv.z),
                                __float2half((v.w-mu)*sc*wv.w + bv.w));
    *(uint2*)(outh + (size_t)row*DM + c0) = make_uint2(*(uint32_t*)&pA, *(uint32_t*)&pB);
}

// ---------------- HMMA 2-term fp16 GEMM: C[M,N] = A[M,K] @ (Bhi+Blo)[N,K]^T ----------------
// 128x128 tile, BK=32, 3-stage cp.async pipeline, one barrier per k-chunk.
// EPI: 0=plain fp32, 1=fp32+add, 2=bias+gelu -> fp16 out, 3=fp32+bias+add
#define PITCHB   80
#define MATB     (128*PITCHB)     // 10240
#define STAGEB   (3*MATB)         // A, Bhi, Blo = 30720
#define NSTAGE   3
#define GSMEM_BYTES (NSTAGE*STAGEB)  // 92160

template<int EPI>
__global__ void __launch_bounds__(256, 1)
gemm_tc(const __half* __restrict__ A,
        const __half* __restrict__ Bhi, const __half* __restrict__ Blo,
        float* __restrict__ C, int M, int N, int K,
        const float* __restrict__ add, const float* __restrict__ bias,
        __half* __restrict__ Oh)
{
    extern __shared__ __align__(128) char smem[];
    uint32_t sb = smem_u32(smem);
    int tid = threadIdx.x, wid = tid >> 5, lane = tid & 31;
    int bm = blockIdx.y * 128, bn = blockIdx.x * 128;
    int warp_m = wid >> 2, warp_n = wid & 3;
    int nrow_b = N - bn;

    int lr0 = tid >> 2, lc0 = (tid & 3);
    int lr1 = (tid + 256) >> 2, lc1 = (tid & 3);

    const int NK = K >> 5;

    auto issue_load = [&](int kc) {
        uint32_t s0 = sb + (kc % NSTAGE) * STAGEB;
        int k0 = kc << 5;
        {
            size_t ga0 = (size_t)(bm + lr0) * K + k0 + lc0 * 8;
            size_t ga1 = (size_t)(bm + lr1) * K + k0 + lc1 * 8;
            cp_async16(s0 + lr0*PITCHB + lc0*16, A + ga0, 16);
            cp_async16(s0 + lr1*PITCHB + lc1*16, A + ga1, 16);
        }
        {
            int r0 = lr0 < nrow_b ? lr0 : 0;  uint32_t z0 = lr0 < nrow_b ? 16u : 0u;
            int r1 = lr1 < nrow_b ? lr1 : 0;  uint32_t z1 = lr1 < nrow_b ? 16u : 0u;
            size_t gb0 = (size_t)(bn + r0) * K + k0 + lc0 * 8;
            size_t gb1 = (size_t)(bn + r1) * K + k0 + lc1 * 8;
            cp_async16(s0 + 1*MATB + lr0*PITCHB + lc0*16, Bhi + gb0, z0);
            cp_async16(s0 + 1*MATB + lr1*PITCHB + lc1*16, Bhi + gb1, z1);
            cp_async16(s0 + 2*MATB + lr0*PITCHB + lc0*16, Blo + gb0, z0);
            cp_async16(s0 + 2*MATB + lr1*PITCHB + lc1*16, Blo + gb1, z1);
        }
        cp_commit();
    };

    float acc[4][4][4];
    #pragma unroll
    for (int i = 0; i < 4; i++)
        #pragma unroll
        for (int j = 0; j < 4; j++)
            #pragma unroll
            for (int q = 0; q < 4; q++) acc[i][j][q] = 0.f;

    issue_load(0);
    if (NK > 1) issue_load(1);

    int a_row = warp_m * 64 + (lane & 15);
    int a_colb = ((lane >> 4) << 3) * 2;
    int b_row = warp_n * 32 + ((lane >> 4) << 3) + (lane & 7);
    int b_colb = (((lane >> 3) & 1) << 3) * 2;

    for (int kc = 0; kc < NK; kc++) {
        uint32_t s0 = sb + (kc % NSTAGE) * STAGEB;
        if (kc + 1 < NK) cp_wait<1>(); else cp_wait<0>();
        __syncthreads();
        if (kc + 2 < NK) issue_load(kc + 2);

        #pragma unroll
        for (int ks = 0; ks < 2; ks++) {
            uint32_t af[4][4], bh[4][2], bl[4][2];
            #pragma unroll
            for (int mt = 0; mt < 4; mt++) {
                uint32_t ad = s0 + (a_row + mt*16)*PITCHB + a_colb + ks*32;
                ldm_x4(ad, af[mt][0], af[mt][1], af[mt][2], af[mt][3]);
            }
            #pragma unroll
            for (int nh = 0; nh < 2; nh++) {
                uint32_t bd = s0 + 1*MATB + (b_row + nh*16)*PITCHB + b_colb + ks*32;
                ldm_x4(bd, bh[nh*2][0], bh[nh*2][1], bh[nh*2+1][0], bh[nh*2+1][1]);
                ldm_x4(bd + MATB, bl[nh*2][0], bl[nh*2][1], bl[nh*2+1][0], bl[nh*2+1][1]);
            }
            #pragma unroll
            for (int mt = 0; mt < 4; mt++) {
                #pragma unroll
                for (int nt = 0; nt < 4; nt++)
                    mma_f16(acc[mt][nt], af[mt], bh[nt]);
                #pragma unroll
                for (int nt = 0; nt < 4; nt++)
                    mma_f16(acc[mt][nt], af[mt], bl[nt]);
            }
        }
    }

    // epilogue
    int g = lane >> 2, tig = lane & 3;
    #pragma unroll
    for (int mt = 0; mt < 4; mt++) {
        int row0 = bm + warp_m*64 + mt*16 + g;
        #pragma unroll
        for (int nt = 0; nt < 4; nt++) {
            int col = bn + warp_n*32 + nt*8 + tig*2;
            if (col < N) {
                #pragma unroll
                for (int h = 0; h < 2; h++) {
                    int row = row0 + h*8;
                    float v0 = acc[mt][nt][h*2+0];
                    float v1 = acc[mt][nt][h*2+1];
                    size_t idx = (size_t)row * N + col;
                    if (EPI == 1) { v0 += add[idx]; v1 += add[idx+1]; }
                    if (EPI == 3) { v0 += bias[col] + add[idx]; v1 += bias[col+1] + add[idx+1]; }
                    if (EPI == 2) {
                        v0 += bias[col];   v0 = 0.5f*v0*(1.f + erff(v0*0.70710678118f));
                        v1 += bias[col+1]; v1 = 0.5f*v1*(1.f + erff(v1*0.70710678118f));
                        __half2 hp = __halves2half2(__float2half(v0), __float2half(v1));
                        *(uint32_t*)(Oh + idx) = *(uint32_t*)&hp;
                    } else {
                        *(float2*)(C + idx) = make_float2(v0, v1);
                    }
                }
            }
        }
    }
}

// ---------------- conv1d(width4, causal) + SiLU + dt softplus ----------------
__global__ void conv_kernel(const float* __restrict__ conv_w, const float* __restrict__ conv_b,
                            const float* __restrict__ dt_bias)
{
    int r = blockIdx.x;
    int b = r >> 11, l = r & (LSEQ-1);
    for (int c = threadIdx.x; c < CONVDIM; c += 256) {
        float acc = conv_b[c];
        #pragma unroll
        for (int k = 0; k < 4; k++) {
            int ll = l + k - 3;
            if (ll >= 0)
                acc = fmaf(g_zx[(size_t)(b*LSEQ + ll)*DINPROJ + DI + c], conv_w[c*4 + k], acc);
        }
        acc = acc / (1.f + expf(-acc));   // SiLU
        g_xbc[(size_t)r*CONVDIM + c] = acc;
    }
    if (threadIdx.x < NH) {
        int hh = threadIdx.x;
        float raw = g_zx[(size_t)r*DINPROJ + DI + CONVDIM + hh] + dt_bias[hh];
        g_dt[r*NH + hh] = (raw > 20.f) ? raw : log1pf(expf(raw));
    }
}

// ---------------- selective scan: one block per (batch, head) ----------------
__global__ void __launch_bounds__(256) scan_kernel(const float* __restrict__ A_log,
                                                   const float* __restrict__ Dvec)
{
    int bh = blockIdx.x;
    int b = bh >> 5, h = bh & 31;
    int t = threadIdx.x;
    int p = t >> 2, nq = t & 3;

    float A_h = -expf(A_log[h]);
    float Dh  = Dvec[h];

    __shared__ float sX[2][64], sB[2][64], sC[2][64];
    __shared__ float sdt[2];

    const size_t base0 = (size_t)(b*LSEQ)*CONVDIM;
    auto load = [&](int buf, int l) {
        size_t rb = base0 + (size_t)l*CONVDIM;
        if (t < 64)        sX[buf][t]       = g_xbc[rb + h*HD + t];
        else if (t < 128)  sB[buf][t-64]    = g_xbc[rb + DI + (t-64)];
        else if (t < 192)  sC[buf][t-128]   = g_xbc[rb + DI + DSTATE + (t-128)];
        else if (t == 192) sdt[buf]         = g_dt[(b*LSEQ + l)*NH + h];
    };

    load(0, 0);
    __syncthreads();

    float st[16];
    #pragma unroll
    for (int i = 0; i < 16; i++) st[i] = 0.f;

    for (int l = 0; l < LSEQ; l++) {
        int buf = l & 1;
        if (l + 1 < LSEQ) load(buf ^ 1, l + 1);

        float dtv  = sdt[buf];
        float dA   = expf(dtv * A_h);
        float xv   = sX[buf][p];
        float coef = dtv * xv;

        const float* Bp = &sB[buf][nq*16];
        const float* Cp = &sC[buf][nq*16];
        float acc = 0.f;
        #pragma unroll
        for (int i = 0; i < 16; i++) {
            float s2 = fmaf(st[i], dA, coef * Bp[i]);
            st[i] = s2;
            acc = fmaf(s2, Cp[i], acc);
        }
        acc += __shfl_xor_sync(0xffffffffu, acc, 1);
        acc += __shfl_xor_sync(0xffffffffu, acc, 2);
        if (nq == 0)
            g_y[(size_t)(b*LSEQ + l)*DI + h*HD + p] = acc + xv * Dh;
        __syncthreads();
    }
}

// ---------------- gate (y * silu(z)) + RMSNorm -> fp16 out ----------------
__global__ void gate_rms_h_kernel(const float* __restrict__ norm_w,
                                  __half* __restrict__ outh)
{
    int r = blockIdx.x;
    size_t zb = (size_t)r*DINPROJ;
    size_t yb = (size_t)r*DI;
    int c0 = threadIdx.x * 8;

    float v[8];
    float ss = 0.f;
    #pragma unroll
    for (int q = 0; q < 2; q++) {
        float4 yv = *(const float4*)(g_y + yb + c0 + q*4);
        float4 zv = *(const float4*)(g_zx + zb + c0 + q*4);
        float* vv = v + q*4;
        vv[0] = yv.x * (zv.x / (1.f + expf(-zv.x)));
        vv[1] = yv.y * (zv.y / (1.f + expf(-zv.y)));
        vv[2] = yv.z * (zv.z / (1.f + expf(-zv.z)));
        vv[3] = yv.w * (zv.w / (1.f + expf(-zv.w)));
        ss += vv[0]*vv[0] + vv[1]*vv[1] + vv[2]*vv[2] + vv[3]*vv[3];
    }
    __shared__ float red[8];
    #pragma unroll
    for (int o = 16; o; o >>= 1) ss += __shfl_xor_sync(0xffffffffu, ss, o);
    if ((threadIdx.x & 31) == 0) red[threadIdx.x >> 5] = ss;
    __syncthreads();
    ss = 0.f;
    #pragma unroll
    for (int i = 0; i < 8; i++) ss += red[i];
    float sc = rsqrtf(ss * (1.f/DI) + EPSF);

    uint32_t hp[4];
    #pragma unroll
    for (int q = 0; q < 4; q++) {
        __half2 hv = __halves2half2(__float2half(v[q*2+0] * sc * norm_w[c0 + q*2+0]),
                                    __float2half(v[q*2+1] * sc * norm_w[c0 + q*2+1]));
        hp[q] = *(uint32_t*)&hv;
    }
    *(uint4*)(outh + yb + c0) = make_uint4(hp[0],hp[1],hp[2],hp[3]);
}

// ---------------- launch ----------------
extern "C" void kernel_launch(void* const* d_in, const int* in_sizes, int n_in,
                              void* d_out, int out_size)
{
    const float* x          = (const float*)d_in[0];
    const float* ln1_w      = (const float*)d_in[1];
    const float* ln1_b      = (const float*)d_in[2];
    const float* in_proj_w  = (const float*)d_in[3];
    const float* conv_w     = (const float*)d_in[4];
    const float* conv_b     = (const float*)d_in[5];
    const float* dt_bias    = (const float*)d_in[6];
    const float* A_log      = (const float*)d_in[7];
    const float* Dvec       = (const float*)d_in[8];
    const float* norm_w     = (const float*)d_in[9];
    const float* out_proj_w = (const float*)d_in[10];
    const float* ln2_w      = (const float*)d_in[11];
    const float* ln2_b      = (const float*)d_in[12];
    const float* mlp_w1     = (const float*)d_in[13];
    const float* mlp_b1     = (const float*)d_in[14];
    const float* mlp_w2     = (const float*)d_in[15];
    const float* mlp_b2     = (const float*)d_in[16];
    float* out = (float*)d_out;

    float *zxp, *yp, *x1p;
    cudaGetSymbolAddress((void**)&zxp,  g_zx);
    cudaGetSymbolAddress((void**)&yp,   g_y);
    cudaGetSymbolAddress((void**)&x1p,  g_x1);

    __half *wip_h, *wip_l, *wop_h, *wop_l, *wm1_h, *wm1_l, *wm2_h, *wm2_l;
    __half *aln1, *ay, *aln2, *amlp;
    cudaGetSymbolAddress((void**)&wip_h, w_ip_hi);  cudaGetSymbolAddress((void**)&wip_l, w_ip_lo);
    cudaGetSymbolAddress((void**)&wop_h, w_op_hi);  cudaGetSymbolAddress((void**)&wop_l, w_op_lo);
    cudaGetSymbolAddress((void**)&wm1_h, w_m1_hi);  cudaGetSymbolAddress((void**)&wm1_l, w_m1_lo);
    cudaGetSymbolAddress((void**)&wm2_h, w_m2_hi);  cudaGetSymbolAddress((void**)&wm2_l, w_m2_lo);
    cudaGetSymbolAddress((void**)&aln1, a_ln1);
    cudaGetSymbolAddress((void**)&ay,   a_y);
    cudaGetSymbolAddress((void**)&aln2, a_ln2);
    cudaGetSymbolAddress((void**)&amlp, a_mlp);

    cudaFuncSetAttribute(gemm_tc<0>, cudaFuncAttributeMaxDynamicSharedMemorySize, GSMEM_BYTES);
    cudaFuncSetAttribute(gemm_tc<1>, cudaFuncAttributeMaxDynamicSharedMemorySize, GSMEM_BYTES);
    cudaFuncSetAttribute(gemm_tc<2>, cudaFuncAttributeMaxDynamicSharedMemorySize, GSMEM_BYTES);
    cudaFuncSetAttribute(gemm_tc<3>, cudaFuncAttributeMaxDynamicSharedMemorySize, GSMEM_BYTES);

    // weight splits
    cvt_kernel<<<512, 256>>>((const float4*)in_proj_w,  (uint2*)wip_h, (uint2*)wip_l, (size_t)DINPROJ*DM/4);
    cvt_kernel<<<512, 256>>>((const float4*)out_proj_w, (uint2*)wop_h, (uint2*)wop_l, (size_t)DM*DI/4);
    cvt_kernel<<<512, 256>>>((const float4*)mlp_w1,     (uint2*)wm1_h, (uint2*)wm1_l, (size_t)4*DM*DM/4);
    cvt_kernel<<<512, 256>>>((const float4*)mlp_w2,     (uint2*)wm2_h, (uint2*)wm2_l, (size_t)DM*4*DM/4);

    // 1. LN1 -> fp16
    ln_h_kernel<<<ROWS, 256>>>(x, ln1_w, ln1_b, aln1);
    // 2. zxbcdt = ln1 @ in_proj_w^T
    {
        dim3 g((DINPROJ + 127)/128, ROWS/128);
        gemm_tc<0><<<g, 256, GSMEM_BYTES>>>(aln1, wip_h, wip_l, zxp,
                                            ROWS, DINPROJ, DM, nullptr, nullptr, nullptr);
    }
    // 3. conv + silu + dt softplus
    conv_kernel<<<ROWS, 256>>>(conv_w, conv_b, dt_bias);
    // 4. selective scan (+ D skip)
    scan_kernel<<<BATCH*NH, 256>>>(A_log, Dvec);
    // 5. gate + rmsnorm -> fp16
    gate_rms_h_kernel<<<ROWS, 256>>>(norm_w, ay);
    // 6. x1 = x + y @ out_proj_w^T
    {
        dim3 g((DM + 127)/128, ROWS/128);
        gemm_tc<1><<<g, 256, GSMEM_BYTES>>>(ay, wop_h, wop_l, x1p,
                                            ROWS, DM, DI, x, nullptr, nullptr);
    }
    // 7. LN2 -> fp16
    ln_h_kernel<<<ROWS, 256>>>(x1p, ln2_w, ln2_b, aln2);
    // 8. mlp1 = gelu(ln2 @ mlp_w1^T + b1) -> fp16 directly
    {
        dim3 g((4*DM + 127)/128, ROWS/128);
        gemm_tc<2><<<g, 256, GSMEM_BYTES>>>(aln2, wm1_h, wm1_l, nullptr,
                                            ROWS, 4*DM, DM, nullptr, mlp_b1, amlp);
    }
    // 9. out = x1 + mlp1 @ mlp_w2^T + b2
    {
        dim3 g((DM + 127)/128, ROWS/128);
        gemm_tc<3><<<g, 256, GSMEM_BYTES>>>(amlp, wm2_h, wm2_l, out,
                                            ROWS, DM, 4*DM, x1p, mlp_b2, nullptr);
    }
}

// round 9
// speedup vs baseline: 2.1045x; 1.2078x over previous
#include <cuda_runtime.h>
#include <cuda_fp16.h>
#include <math.h>
#include <stdint.h>

#define BATCH   2
#define LSEQ    2048
#define DM      1024
#define DI      2048
#define DSTATE  64
#define HD      64
#define NH      32
#define CONVDIM 2176
#define DINPROJ 4256
#define ROWS    (BATCH*LSEQ)
#define EPSF    1e-5f

// ---------------- fp32 scratch ----------------
__device__ float g_zx [(size_t)ROWS*DINPROJ];
__device__ float g_xbc[(size_t)ROWS*CONVDIM];
__device__ float g_dt [(size_t)ROWS*NH];
__device__ float g_y  [(size_t)ROWS*DI];
__device__ float g_x1 [(size_t)ROWS*DM];

// ---------------- fp16 scratch ----------------
__device__ __half w_ip[(size_t)DINPROJ*DM];
__device__ __half w_op[(size_t)DM*DI];
__device__ __half w_m1[(size_t)4*DM*DM];
__device__ __half w_m2[(size_t)DM*4*DM];
__device__ __half a_ln1[(size_t)ROWS*DM];
__device__ __half a_y  [(size_t)ROWS*DI];
__device__ __half a_ln2[(size_t)ROWS*DM];
__device__ __half a_mlp[(size_t)ROWS*4*DM];

// ---------------- helpers ----------------
__device__ __forceinline__ uint32_t smem_u32(const void* p) {
    uint32_t a;
    asm("{ .reg .u64 t; cvta.to.shared.u64 t, %1; cvt.u32.u64 %0, t; }" : "=r"(a) : "l"(p));
    return a;
}
__device__ __forceinline__ void cp_async16(uint32_t saddr, const void* gaddr, uint32_t sz) {
    asm volatile("cp.async.cg.shared.global [%0], [%1], 16, %2;"
                 :: "r"(saddr), "l"(gaddr), "r"(sz));
}
__device__ __forceinline__ void cp_commit() { asm volatile("cp.async.commit_group;"); }
template<int N> __device__ __forceinline__ void cp_wait() {
    asm volatile("cp.async.wait_group %0;" :: "n"(N));
}
__device__ __forceinline__ void ldm_x4(uint32_t addr, uint32_t& r0, uint32_t& r1,
                                       uint32_t& r2, uint32_t& r3) {
    asm volatile("ldmatrix.sync.aligned.m8n8.x4.shared.b16 {%0,%1,%2,%3}, [%4];"
                 : "=r"(r0), "=r"(r1), "=r"(r2), "=r"(r3) : "r"(addr));
}
__device__ __forceinline__ void mma_f16(float* c, const uint32_t* a, const uint32_t* b) {
    asm volatile(
        "mma.sync.aligned.m16n8k16.row.col.f32.f16.f16.f32 "
        "{%0,%1,%2,%3}, {%4,%5,%6,%7}, {%8,%9}, {%0,%1,%2,%3};"
        : "+f"(c[0]), "+f"(c[1]), "+f"(c[2]), "+f"(c[3])
        : "r"(a[0]), "r"(a[1]), "r"(a[2]), "r"(a[3]), "r"(b[0]), "r"(b[1]));
}

// ---------------- vectorized fp32 -> fp16 convert ----------------
__global__ void cvt_kernel(const float4* __restrict__ in, uint2* __restrict__ outh, size_t n4)
{
    size_t i = (size_t)blockIdx.x * blockDim.x + threadIdx.x;
    size_t stride = (size_t)gridDim.x * blockDim.x;
    for (; i < n4; i += stride) {
        float4 v = in[i];
        __half2 pA = __halves2half2(__float2half(v.x), __float2half(v.y));
        __half2 pB = __halves2half2(__float2half(v.z), __float2half(v.w));
        outh[i] = make_uint2(*(uint32_t*)&pA, *(uint32_t*)&pB);
    }
}

// ---------------- layernorm -> fp16 out ----------------
__global__ void ln_h_kernel(const float* __restrict__ in, const float* __restrict__ w,
                            const float* __restrict__ b, __half* __restrict__ outh)
{
    int row = blockIdx.x;
    const float* x = in + (size_t)row*DM;
    int c0 = threadIdx.x * 4;
    float4 v = *(const float4*)(x + c0);
    float s  = v.x + v.y + v.z + v.w;
    float ss = v.x*v.x + v.y*v.y + v.z*v.z + v.w*v.w;
    __shared__ float red0[8], red1[8];
    #pragma unroll
    for (int o = 16; o; o >>= 1) {
        s  += __shfl_xor_sync(0xffffffffu, s, o);
        ss += __shfl_xor_sync(0xffffffffu, ss, o);
    }
    int warp = threadIdx.x >> 5, lane = threadIdx.x & 31;
    if (lane == 0) { red0[warp] = s; red1[warp] = ss; }
    __syncthreads();
    s = 0.f; ss = 0.f;
    #pragma unroll
    for (int i = 0; i < 8; i++) { s += red0[i]; ss += red1[i]; }
    float mu  = s * (1.f/DM);
    float var = ss * (1.f/DM) - mu*mu;
    float sc  = rsqrtf(var + EPSF);
    float4 wv = *(const float4*)(w + c0);
    float4 bv = *(const float4*)(b + c0);
    __half2 pA = __halves2half2(__float2half((v.x-mu)*sc*wv.x + bv.x),
                                __float2half((v.y-mu)*sc*wv.y + bv.y));
    __half2 pB = __halves2half2(__float2half((v.z-mu)*sc*wv.z + bv.z),
                                __float2half((v.w-mu)*sc*wv.w + bv.w));
    *(uint2*)(outh + (size_t)row*DM + c0) = make_uint2(*(uint32_t*)&pA, *(uint32_t*)&pB);
}

// ---------------- HMMA fp16 GEMM: C[M,N] = A[M,K] @ B[N,K]^T ----------------
// 128x128 tile, BK=64 per stage, 3-stage cp.async pipeline, one barrier per chunk.
// smem pitch 144B (64 fp16 = 128B data + 16B pad): conflict-free stores + ldmatrix.
// EPI: 0=plain fp32, 1=fp32+add, 2=bias+gelu -> fp16 out, 3=fp32+bias+add
#define PITCHB   144
#define MATB     (128*PITCHB)     // 18432
#define STAGEB   (2*MATB)         // A, B = 36864
#define NSTAGE   3
#define GSMEM_BYTES (NSTAGE*STAGEB)  // 110592

template<int EPI>
__global__ void __launch_bounds__(256, 1)
gemm_tc(const __half* __restrict__ A, const __half* __restrict__ B,
        float* __restrict__ C, int M, int N, int K,
        const float* __restrict__ add, const float* __restrict__ bias,
        __half* __restrict__ Oh)
{
    extern __shared__ __align__(128) char smem[];
    uint32_t sb = smem_u32(smem);
    int tid = threadIdx.x, wid = tid >> 5, lane = tid & 31;
    int bm = blockIdx.y * 128, bn = blockIdx.x * 128;
    int warp_m = wid >> 2, warp_n = wid & 3;
    int nrow_b = N - bn;

    const int NK = K >> 6;   // BK=64 chunks

    auto issue_load = [&](int kc) {
        uint32_t s0 = sb + (kc % NSTAGE) * STAGEB;
        int k0 = kc << 6;
        #pragma unroll
        for (int i = 0; i < 4; i++) {
            int chunk = tid + i * 256;       // 0..1023
            int row = chunk >> 3, col = chunk & 7;
            uint32_t sa = s0 + row * PITCHB + col * 16;
            size_t ga = (size_t)(bm + row) * K + k0 + col * 8;
            cp_async16(sa, A + ga, 16);
            int rb = row < nrow_b ? row : 0;
            uint32_t zb = row < nrow_b ? 16u : 0u;
            size_t gb = (size_t)(bn + rb) * K + k0 + col * 8;
            cp_async16(sa + MATB, B + gb, zb);
        }
        cp_commit();
    };

    float acc[4][4][4];
    #pragma unroll
    for (int i = 0; i < 4; i++)
        #pragma unroll
        for (int j = 0; j < 4; j++)
            #pragma unroll
            for (int q = 0; q < 4; q++) acc[i][j][q] = 0.f;

    issue_load(0);
    if (NK > 1) issue_load(1);

    int a_row = warp_m * 64 + (lane & 15);
    int a_colb = (lane >> 4) * 16;
    int b_row = warp_n * 32 + ((lane >> 4) << 3) + (lane & 7);
    int b_colb = ((lane >> 3) & 1) * 16;

    for (int kc = 0; kc < NK; kc++) {
        uint32_t s0 = sb + (kc % NSTAGE) * STAGEB;
        if (kc + 1 < NK) cp_wait<1>(); else cp_wait<0>();
        __syncthreads();
        if (kc + 2 < NK) issue_load(kc + 2);

        #pragma unroll
        for (int ks = 0; ks < 4; ks++) {
            uint32_t af[4][4], bf[4][2];
            #pragma unroll
            for (int mt = 0; mt < 4; mt++) {
                uint32_t ad = s0 + (a_row + mt*16)*PITCHB + a_colb + ks*32;
                ldm_x4(ad, af[mt][0], af[mt][1], af[mt][2], af[mt][3]);
            }
            #pragma unroll
            for (int nh = 0; nh < 2; nh++) {
                uint32_t bd = s0 + MATB + (b_row + nh*16)*PITCHB + b_colb + ks*32;
                ldm_x4(bd, bf[nh*2][0], bf[nh*2][1], bf[nh*2+1][0], bf[nh*2+1][1]);
            }
            #pragma unroll
            for (int mt = 0; mt < 4; mt++)
                #pragma unroll
                for (int nt = 0; nt < 4; nt++)
                    mma_f16(acc[mt][nt], af[mt], bf[nt]);
        }
    }

    // epilogue
    int g = lane >> 2, tig = lane & 3;
    #pragma unroll
    for (int mt = 0; mt < 4; mt++) {
        int row0 = bm + warp_m*64 + mt*16 + g;
        #pragma unroll
        for (int nt = 0; nt < 4; nt++) {
            int col = bn + warp_n*32 + nt*8 + tig*2;
            if (col < N) {
                #pragma unroll
                for (int h = 0; h < 2; h++) {
                    int row = row0 + h*8;
                    float v0 = acc[mt][nt][h*2+0];
                    float v1 = acc[mt][nt][h*2+1];
                    size_t idx = (size_t)row * N + col;
                    if (EPI == 1) { v0 += add[idx]; v1 += add[idx+1]; }
                    if (EPI == 3) { v0 += bias[col] + add[idx]; v1 += bias[col+1] + add[idx+1]; }
                    if (EPI == 2) {
                        v0 += bias[col];   v0 = 0.5f*v0*(1.f + erff(v0*0.70710678118f));
                        v1 += bias[col+1]; v1 = 0.5f*v1*(1.f + erff(v1*0.70710678118f));
                        __half2 hp = __halves2half2(__float2half(v0), __float2half(v1));
                        *(uint32_t*)(Oh + idx) = *(uint32_t*)&hp;
                    } else {
                        *(float2*)(C + idx) = make_float2(v0, v1);
                    }
                }
            }
        }
    }
}

// ---------------- conv1d(width4, causal) + SiLU + dt softplus ----------------
__global__ void conv_kernel(const float* __restrict__ conv_w, const float* __restrict__ conv_b,
                            const float* __restrict__ dt_bias)
{
    int r = blockIdx.x;
    int b = r >> 11, l = r & (LSEQ-1);
    for (int c = threadIdx.x; c < CONVDIM; c += 256) {
        float acc = conv_b[c];
        #pragma unroll
        for (int k = 0; k < 4; k++) {
            int ll = l + k - 3;
            if (ll >= 0)
                acc = fmaf(g_zx[(size_t)(b*LSEQ + ll)*DINPROJ + DI + c], conv_w[c*4 + k], acc);
        }
        acc = acc / (1.f + expf(-acc));   // SiLU
        g_xbc[(size_t)r*CONVDIM + c] = acc;
    }
    if (threadIdx.x < NH) {
        int hh = threadIdx.x;
        float raw = g_zx[(size_t)r*DINPROJ + DI + CONVDIM + hh] + dt_bias[hh];
        g_dt[r*NH + hh] = (raw > 20.f) ? raw : log1pf(expf(raw));
    }
}

// ---------------- selective scan: one block per (batch, head) ----------------
__global__ void __launch_bounds__(256) scan_kernel(const float* __restrict__ A_log,
                                                   const float* __restrict__ Dvec)
{
    int bh = blockIdx.x;
    int b = bh >> 5, h = bh & 31;
    int t = threadIdx.x;
    int p = t >> 2, nq = t & 3;

    float A_h = -expf(A_log[h]);
    float Dh  = Dvec[h];

    __shared__ float sX[2][64], sB[2][64], sC[2][64];
    __shared__ float sdt[2];

    const size_t base0 = (size_t)(b*LSEQ)*CONVDIM;
    auto load = [&](int buf, int l) {
        size_t rb = base0 + (size_t)l*CONVDIM;
        if (t < 64)        sX[buf][t]       = g_xbc[rb + h*HD + t];
        else if (t < 128)  sB[buf][t-64]    = g_xbc[rb + DI + (t-64)];
        else if (t < 192)  sC[buf][t-128]   = g_xbc[rb + DI + DSTATE + (t-128)];
        else if (t == 192) sdt[buf]         = g_dt[(b*LSEQ + l)*NH + h];
    };

    load(0, 0);
    __syncthreads();

    float st[16];
    #pragma unroll
    for (int i = 0; i < 16; i++) st[i] = 0.f;

    for (int l = 0; l < LSEQ; l++) {
        int buf = l & 1;
        if (l + 1 < LSEQ) load(buf ^ 1, l + 1);

        float dtv  = sdt[buf];
        float dA   = expf(dtv * A_h);
        float xv   = sX[buf][p];
        float coef = dtv * xv;

        const float* Bp = &sB[buf][nq*16];
        const float* Cp = &sC[buf][nq*16];
        float acc = 0.f;
        #pragma unroll
        for (int i = 0; i < 16; i++) {
            float s2 = fmaf(st[i], dA, coef * Bp[i]);
            st[i] = s2;
            acc = fmaf(s2, Cp[i], acc);
        }
        acc += __shfl_xor_sync(0xffffffffu, acc, 1);
        acc += __shfl_xor_sync(0xffffffffu, acc, 2);
        if (nq == 0)
            g_y[(size_t)(b*LSEQ + l)*DI + h*HD + p] = acc + xv * Dh;
        __syncthreads();
    }
}

// ---------------- gate (y * silu(z)) + RMSNorm -> fp16 out ----------------
__global__ void gate_rms_h_kernel(const float* __restrict__ norm_w,
                                  __half* __restrict__ outh)
{
    int r = blockIdx.x;
    size_t zb = (size_t)r*DINPROJ;
    size_t yb = (size_t)r*DI;
    int c0 = threadIdx.x * 8;

    float v[8];
    float ss = 0.f;
    #pragma unroll
    for (int q = 0; q < 2; q++) {
        float4 yv = *(const float4*)(g_y + yb + c0 + q*4);
        float4 zv = *(const float4*)(g_zx + zb + c0 + q*4);
        float* vv = v + q*4;
        vv[0] = yv.x * (zv.x / (1.f + expf(-zv.x)));
        vv[1] = yv.y * (zv.y / (1.f + expf(-zv.y)));
        vv[2] = yv.z * (zv.z / (1.f + expf(-zv.z)));
        vv[3] = yv.w * (zv.w / (1.f + expf(-zv.w)));
        ss += vv[0]*vv[0] + vv[1]*vv[1] + vv[2]*vv[2] + vv[3]*vv[3];
    }
    __shared__ float red[8];
    #pragma unroll
    for (int o = 16; o; o >>= 1) ss += __shfl_xor_sync(0xffffffffu, ss, o);
    if ((threadIdx.x & 31) == 0) red[threadIdx.x >> 5] = ss;
    __syncthreads();
    ss = 0.f;
    #pragma unroll
    for (int i = 0; i < 8; i++) ss += red[i];
    float sc = rsqrtf(ss * (1.f/DI) + EPSF);

    uint32_t hp[4];
    #pragma unroll
    for (int q = 0; q < 4; q++) {
        __half2 hv = __halves2half2(__float2half(v[q*2+0] * sc * norm_w[c0 + q*2+0]),
                                    __float2half(v[q*2+1] * sc * norm_w[c0 + q*2+1]));
        hp[q] = *(uint32_t*)&hv;
    }
    *(uint4*)(outh + yb + c0) = make_uint4(hp[0],hp[1],hp[2],hp[3]);
}

// ---------------- launch ----------------
extern "C" void kernel_launch(void* const* d_in, const int* in_sizes, int n_in,
                              void* d_out, int out_size)
{
    const float* x          = (const float*)d_in[0];
    const float* ln1_w      = (const float*)d_in[1];
    const float* ln1_b      = (const float*)d_in[2];
    const float* in_proj_w  = (const float*)d_in[3];
    const float* conv_w     = (const float*)d_in[4];
    const float* conv_b     = (const float*)d_in[5];
    const float* dt_bias    = (const float*)d_in[6];
    const float* A_log      = (const float*)d_in[7];
    const float* Dvec       = (const float*)d_in[8];
    const float* norm_w     = (const float*)d_in[9];
    const float* out_proj_w = (const float*)d_in[10];
    const float* ln2_w      = (const float*)d_in[11];
    const float* ln2_b      = (const float*)d_in[12];
    const float* mlp_w1     = (const float*)d_in[13];
    const float* mlp_b1     = (const float*)d_in[14];
    const float* mlp_w2     = (const float*)d_in[15];
    const float* mlp_b2     = (const float*)d_in[16];
    float* out = (float*)d_out;

    float *zxp, *yp, *x1p;
    cudaGetSymbolAddress((void**)&zxp,  g_zx);
    cudaGetSymbolAddress((void**)&yp,   g_y);
    cudaGetSymbolAddress((void**)&x1p,  g_x1);

    __half *wip, *wop, *wm1, *wm2, *aln1, *ay, *aln2, *amlp;
    cudaGetSymbolAddress((void**)&wip, w_ip);
    cudaGetSymbolAddress((void**)&wop, w_op);
    cudaGetSymbolAddress((void**)&wm1, w_m1);
    cudaGetSymbolAddress((void**)&wm2, w_m2);
    cudaGetSymbolAddress((void**)&aln1, a_ln1);
    cudaGetSymbolAddress((void**)&ay,   a_y);
    cudaGetSymbolAddress((void**)&aln2, a_ln2);
    cudaGetSymbolAddress((void**)&amlp, a_mlp);

    cudaFuncSetAttribute(gemm_tc<0>, cudaFuncAttributeMaxDynamicSharedMemorySize, GSMEM_BYTES);
    cudaFuncSetAttribute(gemm_tc<1>, cudaFuncAttributeMaxDynamicSharedMemorySize, GSMEM_BYTES);
    cudaFuncSetAttribute(gemm_tc<2>, cudaFuncAttributeMaxDynamicSharedMemorySize, GSMEM_BYTES);
    cudaFuncSetAttribute(gemm_tc<3>, cudaFuncAttributeMaxDynamicSharedMemorySize, GSMEM_BYTES);

    // weight converts
    cvt_kernel<<<512, 256>>>((const float4*)in_proj_w,  (uint2*)wip, (size_t)DINPROJ*DM/4);
    cvt_kernel<<<512, 256>>>((const float4*)out_proj_w, (uint2*)wop, (size_t)DM*DI/4);
    cvt_kernel<<<512, 256>>>((const float4*)mlp_w1,     (uint2*)wm1, (size_t)4*DM*DM/4);
    cvt_kernel<<<512, 256>>>((const float4*)mlp_w2,     (uint2*)wm2, (size_t)DM*4*DM/4);

    // 1. LN1 -> fp16
    ln_h_kernel<<<ROWS, 256>>>(x, ln1_w, ln1_b, aln1);
    // 2. zxbcdt = ln1 @ in_proj_w^T
    {
        dim3 g((DINPROJ + 127)/128, ROWS/128);
        gemm_tc<0><<<g, 256, GSMEM_BYTES>>>(aln1, wip, zxp,
                                            ROWS, DINPROJ, DM, nullptr, nullptr, nullptr);
    }
    // 3. conv + silu + dt softplus
    conv_kernel<<<ROWS, 256>>>(conv_w, conv_b, dt_bias);
    // 4. selective scan (+ D skip)
    scan_kernel<<<BATCH*NH, 256>>>(A_log, Dvec);
    // 5. gate + rmsnorm -> fp16
    gate_rms_h_kernel<<<ROWS, 256>>>(norm_w, ay);
    // 6. x1 = x + y @ out_proj_w^T
    {
        dim3 g((DM + 127)/128, ROWS/128);
        gemm_tc<1><<<g, 256, GSMEM_BYTES>>>(ay, wop, x1p,
                                            ROWS, DM, DI, x, nullptr, nullptr);
    }
    // 7. LN2 -> fp16
    ln_h_kernel<<<ROWS, 256>>>(x1p, ln2_w, ln2_b, aln2);
    // 8. mlp1 = gelu(ln2 @ mlp_w1^T + b1) -> fp16 directly
    {
        dim3 g((4*DM + 127)/128, ROWS/128);
        gemm_tc<2><<<g, 256, GSMEM_BYTES>>>(aln2, wm1, nullptr,
                                            ROWS, 4*DM, DM, nullptr, mlp_b1, amlp);
    }
    // 9. out = x1 + mlp1 @ mlp_w2^T + b2
    {
        dim3 g((DM + 127)/128, ROWS/128);
        gemm_tc<3><<<g, 256, GSMEM_BYTES>>>(amlp, wm2, out,
                                            ROWS, DM, 4*DM, x1p, mlp_b2, nullptr);
    }
}